// round 11
// baseline (speedup 1.0000x reference)
#include <cuda_runtime.h>
#include <cstdint>

#define SEQ   2048
#define BATCH 128
#define INP   64
#define HID   256
#define GH    1024   // 4*HID
#define OUTD  64

typedef unsigned long long ull;

// packed 2xfp32 FMA (B300: FFMA-3reg is half rate; f32x2 restores full rate)
#define FMA2(d, a, b) asm("fma.rn.f32x2 %0, %1, %2, %0;" : "+l"(d) : "l"(a), "l"(b))

__device__ __forceinline__ float hsum2(ull v) {
    float2 f = *(float2*)&v;
    return f.x + f.y;
}

// ---------------- scratch (static device arrays; no cudaMalloc) --------
__device__ float g_hs[(size_t)SEQ * BATCH * HID];  // h history (streamed)

// =============================================================
// Kernel B: persistent fused LSTM scan, cluster-of-8, mbarrier
// publish/pull exchange (no fences, no global atomics, no
// cluster.sync in the loop).
// 128 CTAs = 16 bgroups(8 b) x 8 ugroups(32 u / 128 gate rows).
// W_hh (134KB) + W_ih (42KB) resident in SMEM; x double-buffered.
// Per step: fused GEMV -> gates -> STS own slice to Hnew[par]
// -> remote mbarrier arrives (count 8) -> try_wait local
// -> DSMEM pull of 7 peer slices -> next step.
// =============================================================
#define WS   268   // W_hh row stride (floats) = 3*KSK + 64
#define KSK  68    // W_hh/H ks-slice skew
#define HSK  548   // H ks-slice stride = 8*68 + 4
#define LST  132   // L batch stride
#define WXS  84    // W_ih row stride (floats)
#define KSX  20    // W_ih/x ks-slice skew
#define XSK  164   // x ks-slice stride = 8*20 + 4
#define XBUF (4 * XSK)   // 656 floats per x buffer

#define SM_W    0
#define SM_WX   (128 * WS)             // 34304
#define SM_H    (SM_WX + 128 * WXS)    // 45056
#define SM_L    (SM_H + 4 * HSK)       // 47248
#define SM_X    (SM_L + 8 * LST)       // 48304
#define SM_HN   (SM_X + 2 * XBUF)      // 49616 : Hnew[2][256]
#define SM_MB   (SM_HN + 512)          // 50128 : 2 x u64 mbarriers
#define SM_TOT  (SM_MB + 4)            // 50132 floats = 200528 B

__global__ void __launch_bounds__(512, 1) __cluster_dims__(8, 1, 1)
k_lstm(const float* __restrict__ x, const float* __restrict__ h0,
       const float* __restrict__ c0, const float* __restrict__ Whh,
       const float* __restrict__ Wih, const float* __restrict__ bias)
{
    extern __shared__ float smR[];
    float* Wsm  = smR + SM_W;    // W_hh [row 0..127][ks*68 + k]
    float* Wxsm = smR + SM_WX;   // W_ih [row 0..127][ks*20 + k]
    float* Hsm  = smR + SM_H;    // h    [ks][b*68 + k]
    float* Lsm  = smR + SM_L;    // lin  [b][row]
    float* Xsm  = smR + SM_X;    // x    [par][ks][b*20 + k]
    float* Hnew = smR + SM_HN;   // published h slice [par][b*32 + u]

    const int t      = threadIdx.x;
    const int bgrp   = blockIdx.x >> 3;      // 0..15
    const int myrank = blockIdx.x & 7;       // cluster rank
    const int b0g    = bgrp << 3;            // global batch base
    const int u0     = myrank << 5;          // global unit base

    const int w    = t >> 5, lane = t & 31;
    const int rp   = (w << 2) + (lane >> 3);     // row pair 0..63
    const int ks   = (lane >> 1) & 3;            // K quarter
    const int bp   = lane & 1;                   // batch half

    const uint32_t smem_base = (uint32_t)__cvta_generic_to_shared(smR);
    const uint32_t mbar_addr = smem_base + SM_MB * 4;
    const uint32_t hnew_off  = (uint32_t)SM_HN * 4;

    // ---- mbarrier init (count 8 = one arrive from each rank) ----
    if (t == 0) {
        asm volatile("mbarrier.init.shared.b64 [%0], 8;" :: "r"(mbar_addr) : "memory");
        asm volatile("mbarrier.init.shared.b64 [%0], 8;" :: "r"(mbar_addr + 8) : "memory");
    }

    // ---- load W_hh slice into SMEM once (R8-proven layout) ----
    for (int idx = t; idx < 128 * 64; idx += 512) {
        int r = idx >> 6, c4 = idx & 63;
        int grow = ((r >> 5) << 8) + u0 + (r & 31);
        float4 v = ((const float4*)Whh)[(size_t)grow * 64 + c4];
        int kss = c4 >> 4, kk = (c4 & 15) << 2;
        *(float4*)(Wsm + r * WS + kss * KSK + kk) = v;
    }
    // ---- load W_ih slice into SMEM once ----
    for (int idx = t; idx < 128 * 16; idx += 512) {
        int r = idx >> 4, c4 = idx & 15;
        int grow = ((r >> 5) << 8) + u0 + (r & 31);
        float4 v = ((const float4*)Wih)[(size_t)grow * 16 + c4];
        int kss = c4 >> 2, kk = (c4 & 3) << 2;
        *(float4*)(Wxsm + r * WXS + kss * KSX + kk) = v;
    }
    // ---- init Hsm from h0 ----
    {
        int b = t >> 6, c4 = t & 63;
        float4 v = ((const float4*)h0)[(size_t)(b0g + b) * 64 + c4];
        int kss = c4 >> 4, kk = (c4 & 15) << 2;
        *(float4*)(Hsm + kss * HSK + b * KSK + kk) = v;
    }
    // ---- init Xsm[0] from x[0]; prefetch x[1] into regs (t<128 owns both) ----
    float4 xr = make_float4(0.f, 0.f, 0.f, 0.f);
    if (t < 128) {
        int b = t >> 4, c4 = t & 15;
        float4 v = ((const float4*)x)[(size_t)(b0g + b) * 16 + c4];
        int kss = c4 >> 2, kk = (c4 & 3) << 2;
        *(float4*)(Xsm + kss * XSK + b * KSX + kk) = v;
        xr = ((const float4*)x)[(size_t)(BATCH + b0g + b) * 16 + c4];
    }

    // ---- gate-thread state (t < 256): gb = t>>5, gu = t&31 ----
    const int gb  = t >> 5;
    const int gu  = t & 31;
    const int ugt = u0 + gu;
    float creg = 0.f, bi = 0.f, bf = 0.f, bg = 0.f, bo = 0.f;
    if (t < 256) {
        creg = c0[(size_t)(b0g + gb) * HID + ugt];
        bi = bias[0 * HID + ugt];
        bf = bias[1 * HID + ugt];
        bg = bias[2 * HID + ugt];
        bo = bias[3 * HID + ugt];
    }

    __syncthreads();
    // once: mbarriers + W + H0 visible cluster-wide before any arrives
    asm volatile("barrier.cluster.arrive.aligned;" ::: "memory");
    asm volatile("barrier.cluster.wait.aligned;"   ::: "memory");

    // ---- remote smem bases for all 8 ranks ----
    uint32_t rbase[8];
    #pragma unroll
    for (int p = 0; p < 8; p++)
        asm("mapa.shared::cluster.u32 %0, %1, %2;"
            : "=r"(rbase[p]) : "r"(smem_base), "r"(p));

    const float* Wp  = Wsm  + (rp * 2 + 0) * WS  + ks * KSK;
    const float* Wp1 = Wsm  + (rp * 2 + 1) * WS  + ks * KSK;
    const float* Hp  = Hsm  + ks * HSK + (bp << 2) * KSK;
    const float* Wxp  = Wxsm + (rp * 2 + 0) * WXS + ks * KSX;
    const float* Wxp1 = Wxsm + (rp * 2 + 1) * WXS + ks * KSX;

    #pragma unroll 1
    for (int step = 0; step < SEQ; step++) {
        const int par = step & 1;

        // ---- fused GEMV: [h(256)|x(64)] x [W_hh|W_ih], 2 rows x 4 batches ----
        ull acc00 = 0, acc01 = 0, acc02 = 0, acc03 = 0;
        ull acc10 = 0, acc11 = 0, acc12 = 0, acc13 = 0;
        #pragma unroll
        for (int k4 = 0; k4 < 16; k4++) {
            ulonglong2 w0 = *(const ulonglong2*)(Wp  + k4 * 4);
            ulonglong2 w1 = *(const ulonglong2*)(Wp1 + k4 * 4);
            ulonglong2 hv;
            hv = *(const ulonglong2*)(Hp + 0 * KSK + k4 * 4);
            FMA2(acc00, w0.x, hv.x); FMA2(acc00, w0.y, hv.y);
            FMA2(acc10, w1.x, hv.x); FMA2(acc10, w1.y, hv.y);
            hv = *(const ulonglong2*)(Hp + 1 * KSK + k4 * 4);
            FMA2(acc01, w0.x, hv.x); FMA2(acc01, w0.y, hv.y);
            FMA2(acc11, w1.x, hv.x); FMA2(acc11, w1.y, hv.y);
            hv = *(const ulonglong2*)(Hp + 2 * KSK + k4 * 4);
            FMA2(acc02, w0.x, hv.x); FMA2(acc02, w0.y, hv.y);
            FMA2(acc12, w1.x, hv.x); FMA2(acc12, w1.y, hv.y);
            hv = *(const ulonglong2*)(Hp + 3 * KSK + k4 * 4);
            FMA2(acc03, w0.x, hv.x); FMA2(acc03, w0.y, hv.y);
            FMA2(acc13, w1.x, hv.x); FMA2(acc13, w1.y, hv.y);
        }
        {
            const float* Xq = Xsm + par * XBUF + ks * XSK + (bp << 2) * KSX;
            #pragma unroll
            for (int kx = 0; kx < 4; kx++) {
                ulonglong2 w0 = *(const ulonglong2*)(Wxp  + kx * 4);
                ulonglong2 w1 = *(const ulonglong2*)(Wxp1 + kx * 4);
                ulonglong2 hv;
                hv = *(const ulonglong2*)(Xq + 0 * KSX + kx * 4);
                FMA2(acc00, w0.x, hv.x); FMA2(acc00, w0.y, hv.y);
                FMA2(acc10, w1.x, hv.x); FMA2(acc10, w1.y, hv.y);
                hv = *(const ulonglong2*)(Xq + 1 * KSX + kx * 4);
                FMA2(acc01, w0.x, hv.x); FMA2(acc01, w0.y, hv.y);
                FMA2(acc11, w1.x, hv.x); FMA2(acc11, w1.y, hv.y);
                hv = *(const ulonglong2*)(Xq + 2 * KSX + kx * 4);
                FMA2(acc02, w0.x, hv.x); FMA2(acc02, w0.y, hv.y);
                FMA2(acc12, w1.x, hv.x); FMA2(acc12, w1.y, hv.y);
                hv = *(const ulonglong2*)(Xq + 3 * KSX + kx * 4);
                FMA2(acc03, w0.x, hv.x); FMA2(acc03, w0.y, hv.y);
                FMA2(acc13, w1.x, hv.x); FMA2(acc13, w1.y, hv.y);
            }
        }
        // reduce over the 4 ks lanes (lane bits 1-2) and store to Lsm
        {
            const int r0 = rp * 2, bb = bp << 2;
            float v;
            v = hsum2(acc00); v += __shfl_xor_sync(~0u, v, 2); v += __shfl_xor_sync(~0u, v, 4);
            if (ks == 0) Lsm[(bb + 0) * LST + r0] = v;
            v = hsum2(acc01); v += __shfl_xor_sync(~0u, v, 2); v += __shfl_xor_sync(~0u, v, 4);
            if (ks == 0) Lsm[(bb + 1) * LST + r0] = v;
            v = hsum2(acc02); v += __shfl_xor_sync(~0u, v, 2); v += __shfl_xor_sync(~0u, v, 4);
            if (ks == 0) Lsm[(bb + 2) * LST + r0] = v;
            v = hsum2(acc03); v += __shfl_xor_sync(~0u, v, 2); v += __shfl_xor_sync(~0u, v, 4);
            if (ks == 0) Lsm[(bb + 3) * LST + r0] = v;
            v = hsum2(acc10); v += __shfl_xor_sync(~0u, v, 2); v += __shfl_xor_sync(~0u, v, 4);
            if (ks == 0) Lsm[(bb + 0) * LST + r0 + 1] = v;
            v = hsum2(acc11); v += __shfl_xor_sync(~0u, v, 2); v += __shfl_xor_sync(~0u, v, 4);
            if (ks == 0) Lsm[(bb + 1) * LST + r0 + 1] = v;
            v = hsum2(acc12); v += __shfl_xor_sync(~0u, v, 2); v += __shfl_xor_sync(~0u, v, 4);
            if (ks == 0) Lsm[(bb + 2) * LST + r0 + 1] = v;
            v = hsum2(acc13); v += __shfl_xor_sync(~0u, v, 2); v += __shfl_xor_sync(~0u, v, 4);
            if (ks == 0) Lsm[(bb + 3) * LST + r0 + 1] = v;
        }
        __syncthreads();

        // ---- gate update (t < 256): publish locally, no fence ----
        if (t < 256) {
            const float* Lb = Lsm + gb * LST;
            float iv = Lb[gu]      + bi;
            float fv = Lb[32 + gu] + bf;
            float gv = Lb[64 + gu] + bg;
            float ov = Lb[96 + gu] + bo;
            float ig = 1.f / (1.f + __expf(-iv));
            float fg = 1.f / (1.f + __expf(-fv));
            float gg = tanhf(gv);
            float og = 1.f / (1.f + __expf(-ov));
            float cc = fg * creg + ig * gg;
            creg = cc;
            float hh = og * tanhf(cc);
            Hnew[par * 256 + (gb << 5) + gu] = hh;              // publish for peers
            Hsm[(ugt >> 6) * HSK + gb * KSK + (ugt & 63)] = hh; // own Hsm column
            __stcs(&g_hs[((size_t)step * BATCH + b0g + gb) * HID + ugt], hh);
        }
        // ---- x pipeline: store x[step+1] to Xsm[par^1], prefetch x[step+2] ----
        if (t < 128 && step + 1 < SEQ) {
            int b = t >> 4, c4 = t & 15;
            int kss = c4 >> 2, kk = (c4 & 3) << 2;
            *(float4*)(Xsm + (par ^ 1) * XBUF + kss * XSK + b * KSX + kk) = xr;
            if (step + 2 < SEQ)
                xr = ((const float4*)x)[(size_t)((step + 2) * BATCH + b0g + b) * 16 + c4];
        }
        __syncthreads();   // Hnew complete before arrives

        if (step + 1 < SEQ) {
            // ---- broadcast release-arrives: thread p -> rank p's mbar[par] ----
            if (t < 8) {
                uint32_t ra = rbase[t] + (uint32_t)(SM_MB * 4 + par * 8);
                asm volatile(
                    "mbarrier.arrive.release.cluster.shared::cluster.b64 _, [%0];"
                    :: "r"(ra) : "memory");
            }
            // ---- wait: all 8 ranks published (sleep-based try_wait) ----
            {
                const uint32_t mb = mbar_addr + par * 8;
                const uint32_t ph = (step >> 1) & 1;
                asm volatile(
                    "{\n\t.reg .pred P;\n"
                    "WAITLP%=:\n\t"
                    "mbarrier.try_wait.parity.acquire.cluster.shared::cta.b64 P, [%0], %1;\n\t"
                    "@!P bra WAITLP%=;\n\t}"
                    :: "r"(mb), "r"(ph) : "memory");
            }
            // ---- pull 7 peers' slices from their Hnew[par] into my Hsm ----
            if (t < 448) {
                int p7  = t >> 6;                 // 0..6
                int rem = t & 63;
                int b   = rem >> 3, q = rem & 7;
                int peer = p7 + (p7 >= myrank ? 1 : 0);
                uint32_t ra = rbase[peer] + hnew_off +
                              ((uint32_t)(par * 256 + (b << 5) + (q << 2)) << 2);
                float vx, vy, vz, vw;
                asm volatile("ld.shared::cluster.v4.f32 {%0,%1,%2,%3}, [%4];"
                             : "=f"(vx), "=f"(vy), "=f"(vz), "=f"(vw)
                             : "r"(ra));
                int ug = (peer << 5) + (q << 2);
                *(float4*)(Hsm + (ug >> 6) * HSK + b * KSK + (ug & 63)) =
                    make_float4(vx, vy, vz, vw);
            }
            __syncthreads();
        }
    }
}

// =============================================================
// Kernel C: out = hs @ W_out^T + b_out. M=262144, N=64, K=256.
// =============================================================
__global__ void __launch_bounds__(256) k_gemm_out(const float* __restrict__ Wout,
                                                  const float* __restrict__ bout,
                                                  float* __restrict__ out)
{
    extern __shared__ ulonglong2 smC[];
    ulonglong2* Hs = smC;            // 64 x 19
    ulonglong2* Ws = smC + 64 * 19;  // 64 x 19

    const int t  = threadIdx.x;
    const int m0 = blockIdx.x * 64;
    const int tx = t & 15, ty = t >> 4;

    ull acc[4][4];
    #pragma unroll
    for (int i = 0; i < 4; i++)
        #pragma unroll
        for (int j = 0; j < 4; j++) acc[i][j] = 0ull;

    const ulonglong2* hs4 = (const ulonglong2*)g_hs;
    const ulonglong2* wo4 = (const ulonglong2*)Wout;

    for (int kc = 0; kc < 4; kc++) {
        __syncthreads();
        #pragma unroll
        for (int idx = t; idx < 64 * 16; idx += 256) {
            int rr = idx >> 4, c = idx & 15;
            Hs[rr * 19 + c] = hs4[(size_t)(m0 + rr) * 64 + kc * 16 + c];
            Ws[rr * 19 + c] = wo4[(size_t)rr * 64 + kc * 16 + c];
        }
        __syncthreads();
        #pragma unroll
        for (int k4 = 0; k4 < 16; k4++) {
            ulonglong2 a2[4];
            #pragma unroll
            for (int i = 0; i < 4; i++) a2[i] = Hs[(ty + 16 * i) * 19 + k4];
            #pragma unroll
            for (int j = 0; j < 4; j++) {
                ulonglong2 b2 = Ws[(tx + 16 * j) * 19 + k4];
                #pragma unroll
                for (int i = 0; i < 4; i++) {
                    FMA2(acc[i][j], a2[i].x, b2.x);
                    FMA2(acc[i][j], a2[i].y, b2.y);
                }
            }
        }
    }
    #pragma unroll
    for (int i = 0; i < 4; i++) {
        size_t m = (size_t)(m0 + ty + 16 * i);
        #pragma unroll
        for (int j = 0; j < 4; j++) {
            int n = tx + 16 * j;
            out[m * OUTD + n] = hsum2(acc[i][j]) + __ldg(&bout[n]);
        }
    }
}

// =============================================================
extern "C" void kernel_launch(void* const* d_in, const int* in_sizes, int n_in,
                              void* d_out, int out_size)
{
    (void)in_sizes; (void)n_in; (void)out_size;
    const float* x    = (const float*)d_in[0];
    const float* h0   = (const float*)d_in[1];
    const float* c0   = (const float*)d_in[2];
    const float* Wih  = (const float*)d_in[3];
    const float* Whh  = (const float*)d_in[4];
    const float* b    = (const float*)d_in[5];
    const float* Wout = (const float*)d_in[6];
    const float* bout = (const float*)d_in[7];
    float* out = (float*)d_out;

    const int smB = SM_TOT * 4;             // 200528 B
    const int smC = (64 + 64) * 19 * 16;    // 38912 B

    cudaFuncSetAttribute(k_lstm,     cudaFuncAttributeMaxDynamicSharedMemorySize, smB);
    cudaFuncSetAttribute(k_gemm_out, cudaFuncAttributeMaxDynamicSharedMemorySize, smC);

    k_lstm<<<128, 512, smB>>>(x, h0, c0, Whh, Wih, b);

    k_gemm_out<<<(SEQ * BATCH) / 64, 256, smC>>>(Wout, bout, out);
}

// round 12
// speedup vs baseline: 2.0892x; 2.0892x over previous
#include <cuda_runtime.h>
#include <cstdint>

#define SEQ   2048
#define BATCH 128
#define INP   64
#define HID   256
#define GH    1024   // 4*HID
#define OUTD  64
#define NBG   16     // batch groups (8 batches each)
#define NUG   8      // unit groups  (32 units / 128 gate rows each)

typedef unsigned long long ull;

// packed 2xfp32 FMA (B300: FFMA-3reg is half rate; f32x2 restores full rate)
#define FMA2(d, a, b) asm("fma.rn.f32x2 %0, %1, %2, %0;" : "+l"(d) : "l"(a), "l"(b))

__device__ __forceinline__ float hsum2(ull v) {
    float2 f = *(float2*)&v;
    return f.x + f.y;
}

// ---------------- scratch (static device arrays; no cudaMalloc) --------
__device__ float g_hs[(size_t)SEQ * BATCH * HID];  // h history (streamed)
__device__ float g_hx[2][BATCH * HID];             // hot h exchange (L2)
__device__ unsigned g_flag[NBG * NUG * 32];        // per-CTA publish flags (128B apart)
__device__ unsigned g_cnt;                          // one-shot global barriers
__device__ volatile unsigned g_gen;

// =============================================================
// Single persistent kernel: fused LSTM scan + readout GEMM.
// 128 CTAs = 16 bgroups(8 b) x 8 ugroups(32 u / 128 gate rows).
// Scan: W_hh (134KB) + W_ih (42KB) resident in SMEM, x dbl-buffered.
// Sync per step: flag-based message passing —
//   gates write g_hx[par] (plain L2 stores) -> __syncthreads ->
//   t0: st.release.gpu flag = step+1 -> g_hs history store AFTER
//   (unordered). Consumers: 7 threads ld.acquire.gpu poll peers'
//   flags >= step, then reload g_hx. NO per-warp threadfence, NO
//   central atomic, NO clusters.
// Readout: after one global barrier, same CTAs compute
//   out = hs @ Wout^T + bout (32 x 64-row tiles per CTA).
// =============================================================
#define WS   268   // W_hh row stride (floats) = 3*KSK + 64
#define KSK  68    // W_hh/H ks-slice skew
#define HSK  548   // H ks-slice stride = 8*68 + 4
#define LST  132   // L batch stride
#define WXS  84    // W_ih row stride (floats)
#define KSX  20    // W_ih/x ks-slice skew
#define XSK  164   // x ks-slice stride = 8*20 + 4
#define XBUF (4 * XSK)   // 656 floats per x buffer

#define SM_W    0
#define SM_WX   (128 * WS)             // 34304
#define SM_H    (SM_WX + 128 * WXS)    // 45056
#define SM_L    (SM_H + 4 * HSK)       // 47248
#define SM_X    (SM_L + 8 * LST)       // 48304
// scan layout ends at SM_X + 2*XBUF = 49616.
// readout reuses [0..) for Wout tiles and [SM_H..SM_H+4864) for Hs tile.
#define SM_TOT  50176                  // floats = 200704 B

__device__ __forceinline__ void grid_barrier(int t) {
    if (t == 0) {
        unsigned cur = g_gen;
        __threadfence();
        if (atomicAdd(&g_cnt, 1u) == 127u) {
            atomicExch(&g_cnt, 0u);
            __threadfence();
            g_gen = cur + 1u;
        } else {
            while (g_gen == cur) { }
        }
        __threadfence();
    }
    __syncthreads();
}

__global__ void __launch_bounds__(512, 1)
k_lstm(const float* __restrict__ x, const float* __restrict__ h0,
       const float* __restrict__ c0, const float* __restrict__ Whh,
       const float* __restrict__ Wih, const float* __restrict__ bias,
       const float* __restrict__ Wout, const float* __restrict__ bout,
       float* __restrict__ out)
{
    extern __shared__ float smR[];
    float* Wsm  = smR + SM_W;    // W_hh [row 0..127][ks*68 + k]
    float* Wxsm = smR + SM_WX;   // W_ih [row 0..127][ks*20 + k]
    float* Hsm  = smR + SM_H;    // h    [ks][b*68 + k]
    float* Lsm  = smR + SM_L;    // lin  [b][row]
    float* Xsm  = smR + SM_X;    // x    [par][ks][b*20 + k]

    const int t     = threadIdx.x;
    const int bgrp  = blockIdx.x >> 3;      // 0..15
    const int urank = blockIdx.x & 7;       // 0..7
    const int b0g   = bgrp << 3;            // global batch base
    const int u0    = urank << 5;           // global unit base

    const int w    = t >> 5, lane = t & 31;
    const int rp   = (w << 2) + (lane >> 3);     // row pair 0..63
    const int ks   = (lane >> 1) & 3;            // K quarter
    const int bp   = lane & 1;                   // batch half

    // ---- reset my publish flag, then one-shot global init barrier ----
    unsigned* myflag = &g_flag[(bgrp * NUG + urank) * 32];
    if (t == 0) *myflag = 0u;

    // ---- load W_hh slice into SMEM once (R8-proven layout) ----
    for (int idx = t; idx < 128 * 64; idx += 512) {
        int r = idx >> 6, c4 = idx & 63;
        int grow = ((r >> 5) << 8) + u0 + (r & 31);
        float4 v = ((const float4*)Whh)[(size_t)grow * 64 + c4];
        int kss = c4 >> 4, kk = (c4 & 15) << 2;
        *(float4*)(Wsm + r * WS + kss * KSK + kk) = v;
    }
    // ---- load W_ih slice into SMEM once ----
    for (int idx = t; idx < 128 * 16; idx += 512) {
        int r = idx >> 4, c4 = idx & 15;
        int grow = ((r >> 5) << 8) + u0 + (r & 31);
        float4 v = ((const float4*)Wih)[(size_t)grow * 16 + c4];
        int kss = c4 >> 2, kk = (c4 & 3) << 2;
        *(float4*)(Wxsm + r * WXS + kss * KSX + kk) = v;
    }
    // ---- init Hsm from h0 ----
    {
        int b = t >> 6, c4 = t & 63;
        float4 v = ((const float4*)h0)[(size_t)(b0g + b) * 64 + c4];
        int kss = c4 >> 4, kk = (c4 & 15) << 2;
        *(float4*)(Hsm + kss * HSK + b * KSK + kk) = v;
    }
    // ---- init Xsm[0] from x[0]; prefetch x[1] into regs (t<128) ----
    float4 xr = make_float4(0.f, 0.f, 0.f, 0.f);
    if (t < 128) {
        int b = t >> 4, c4 = t & 15;
        float4 v = ((const float4*)x)[(size_t)(b0g + b) * 16 + c4];
        int kss = c4 >> 2, kk = (c4 & 3) << 2;
        *(float4*)(Xsm + kss * XSK + b * KSX + kk) = v;
        xr = ((const float4*)x)[(size_t)(BATCH + b0g + b) * 16 + c4];
    }

    // ---- gate-thread state (t < 256) ----
    const int gb  = t >> 5;
    const int gu  = t & 31;
    const int ugt = u0 + gu;
    float creg = 0.f, bi = 0.f, bf = 0.f, bg = 0.f, bo = 0.f;
    if (t < 256) {
        creg = c0[(size_t)(b0g + gb) * HID + ugt];
        bi = bias[0 * HID + ugt];
        bf = bias[1 * HID + ugt];
        bg = bias[2 * HID + ugt];
        bo = bias[3 * HID + ugt];
    }

    // flags-zeroed-before-anyone-publishes barrier (replay-safe)
    grid_barrier(t);

    const float* Wp   = Wsm  + (rp * 2 + 0) * WS  + ks * KSK;
    const float* Wp1  = Wsm  + (rp * 2 + 1) * WS  + ks * KSK;
    const float* Hp   = Hsm  + ks * HSK + (bp << 2) * KSK;
    const float* Wxp  = Wxsm + (rp * 2 + 0) * WXS + ks * KSX;
    const float* Wxp1 = Wxsm + (rp * 2 + 1) * WXS + ks * KSX;

    // peer flag pointer for poll threads (t = 1..7)
    const unsigned* peerflag = 0;
    if (t >= 1 && t < 8) {
        int p7 = t - 1;
        int peer = p7 + (p7 >= urank ? 1 : 0);
        peerflag = &g_flag[(bgrp * NUG + peer) * 32];
    }

    #pragma unroll 1
    for (int step = 0; step < SEQ; step++) {
        const int par = step & 1;

        // ---- A: x-part GEMV (independent of h) ----
        ull acc00 = 0, acc01 = 0, acc02 = 0, acc03 = 0;
        ull acc10 = 0, acc11 = 0, acc12 = 0, acc13 = 0;
        {
            const float* Xq = Xsm + par * XBUF + ks * XSK + (bp << 2) * KSX;
            #pragma unroll
            for (int kx = 0; kx < 4; kx++) {
                ulonglong2 w0 = *(const ulonglong2*)(Wxp  + kx * 4);
                ulonglong2 w1 = *(const ulonglong2*)(Wxp1 + kx * 4);
                ulonglong2 hv;
                hv = *(const ulonglong2*)(Xq + 0 * KSX + kx * 4);
                FMA2(acc00, w0.x, hv.x); FMA2(acc00, w0.y, hv.y);
                FMA2(acc10, w1.x, hv.x); FMA2(acc10, w1.y, hv.y);
                hv = *(const ulonglong2*)(Xq + 1 * KSX + kx * 4);
                FMA2(acc01, w0.x, hv.x); FMA2(acc01, w0.y, hv.y);
                FMA2(acc11, w1.x, hv.x); FMA2(acc11, w1.y, hv.y);
                hv = *(const ulonglong2*)(Xq + 2 * KSX + kx * 4);
                FMA2(acc02, w0.x, hv.x); FMA2(acc02, w0.y, hv.y);
                FMA2(acc12, w1.x, hv.x); FMA2(acc12, w1.y, hv.y);
                hv = *(const ulonglong2*)(Xq + 3 * KSX + kx * 4);
                FMA2(acc03, w0.x, hv.x); FMA2(acc03, w0.y, hv.y);
                FMA2(acc13, w1.x, hv.x); FMA2(acc13, w1.y, hv.y);
            }
        }

        // ---- B: wait for peers' h[step-1]; C: reload Hsm ----
        if (step > 0) {
            if (t >= 1 && t < 8) {
                unsigned v;
                do {
                    asm volatile("ld.acquire.gpu.u32 %0, [%1];"
                                 : "=r"(v) : "l"(peerflag) : "memory");
                } while (v < (unsigned)step);
            }
            __syncthreads();
            {
                int b = t >> 6, c4 = t & 63;
                float4 v = *(const float4*)&g_hx[(step - 1) & 1][(b0g + b) * HID + (c4 << 2)];
                int kss = c4 >> 4, kk = (c4 & 15) << 2;
                *(float4*)(Hsm + kss * HSK + b * KSK + kk) = v;
            }
            __syncthreads();
        }

        // ---- D: h-part GEMV accumulate ----
        #pragma unroll
        for (int k4 = 0; k4 < 16; k4++) {
            ulonglong2 w0 = *(const ulonglong2*)(Wp  + k4 * 4);
            ulonglong2 w1 = *(const ulonglong2*)(Wp1 + k4 * 4);
            ulonglong2 hv;
            hv = *(const ulonglong2*)(Hp + 0 * KSK + k4 * 4);
            FMA2(acc00, w0.x, hv.x); FMA2(acc00, w0.y, hv.y);
            FMA2(acc10, w1.x, hv.x); FMA2(acc10, w1.y, hv.y);
            hv = *(const ulonglong2*)(Hp + 1 * KSK + k4 * 4);
            FMA2(acc01, w0.x, hv.x); FMA2(acc01, w0.y, hv.y);
            FMA2(acc11, w1.x, hv.x); FMA2(acc11, w1.y, hv.y);
            hv = *(const ulonglong2*)(Hp + 2 * KSK + k4 * 4);
            FMA2(acc02, w0.x, hv.x); FMA2(acc02, w0.y, hv.y);
            FMA2(acc12, w1.x, hv.x); FMA2(acc12, w1.y, hv.y);
            hv = *(const ulonglong2*)(Hp + 3 * KSK + k4 * 4);
            FMA2(acc03, w0.x, hv.x); FMA2(acc03, w0.y, hv.y);
            FMA2(acc13, w1.x, hv.x); FMA2(acc13, w1.y, hv.y);
        }

        // ---- E: reduce over 4 ks lanes, write Lsm ----
        {
            const int r0 = rp * 2, bb = bp << 2;
            float v;
            v = hsum2(acc00); v += __shfl_xor_sync(~0u, v, 2); v += __shfl_xor_sync(~0u, v, 4);
            if (ks == 0) Lsm[(bb + 0) * LST + r0] = v;
            v = hsum2(acc01); v += __shfl_xor_sync(~0u, v, 2); v += __shfl_xor_sync(~0u, v, 4);
            if (ks == 0) Lsm[(bb + 1) * LST + r0] = v;
            v = hsum2(acc02); v += __shfl_xor_sync(~0u, v, 2); v += __shfl_xor_sync(~0u, v, 4);
            if (ks == 0) Lsm[(bb + 2) * LST + r0] = v;
            v = hsum2(acc03); v += __shfl_xor_sync(~0u, v, 2); v += __shfl_xor_sync(~0u, v, 4);
            if (ks == 0) Lsm[(bb + 3) * LST + r0] = v;
            v = hsum2(acc10); v += __shfl_xor_sync(~0u, v, 2); v += __shfl_xor_sync(~0u, v, 4);
            if (ks == 0) Lsm[(bb + 0) * LST + r0 + 1] = v;
            v = hsum2(acc11); v += __shfl_xor_sync(~0u, v, 2); v += __shfl_xor_sync(~0u, v, 4);
            if (ks == 0) Lsm[(bb + 1) * LST + r0 + 1] = v;
            v = hsum2(acc12); v += __shfl_xor_sync(~0u, v, 2); v += __shfl_xor_sync(~0u, v, 4);
            if (ks == 0) Lsm[(bb + 2) * LST + r0 + 1] = v;
            v = hsum2(acc13); v += __shfl_xor_sync(~0u, v, 2); v += __shfl_xor_sync(~0u, v, 4);
            if (ks == 0) Lsm[(bb + 3) * LST + r0 + 1] = v;
        }
        __syncthreads();

        // ---- F: gates (t<256) publish to g_hx; x-pipe (t<128) ----
        float hh = 0.f;
        if (t < 256) {
            const float* Lb = Lsm + gb * LST;
            float iv = Lb[gu]      + bi;
            float fv = Lb[32 + gu] + bf;
            float gv = Lb[64 + gu] + bg;
            float ov = Lb[96 + gu] + bo;
            float ig = 1.f / (1.f + __expf(-iv));
            float fg = 1.f / (1.f + __expf(-fv));
            float gg = tanhf(gv);
            float og = 1.f / (1.f + __expf(-ov));
            float cc = fg * creg + ig * gg;
            creg = cc;
            hh = og * tanhf(cc);
            g_hx[par][(b0g + gb) * HID + ugt] = hh;   // hot exchange (L2)
        }
        if (t < 128 && step + 1 < SEQ) {
            int b = t >> 4, c4 = t & 15;
            int kss = c4 >> 2, kk = (c4 & 3) << 2;
            *(float4*)(Xsm + (par ^ 1) * XBUF + kss * XSK + b * KSX + kk) = xr;
            if (step + 2 < SEQ)
                xr = ((const float4*)x)[(size_t)((step + 2) * BATCH + b0g + b) * 16 + c4];
        }
        __syncthreads();

        // ---- G: single-thread release publish (orders g_hx only) ----
        if (t == 0) {
            unsigned nv = (unsigned)(step + 1);
            asm volatile("st.release.gpu.u32 [%0], %1;"
                         :: "l"(myflag), "r"(nv) : "memory");
        }
        // ---- H: history store AFTER release (unordered, drains bg) ----
        if (t < 256)
            __stcs(&g_hs[((size_t)step * BATCH + b0g + gb) * HID + ugt], hh);
    }

    // ================= readout: out = hs @ Wout^T + bout =================
    __threadfence();      // make all g_hs stores visible
    grid_barrier(t);

    ulonglong2* WoS = (ulonglong2*)smR;            // [kc][64][19]
    ulonglong2* HsS = (ulonglong2*)(smR + SM_H);   // [64][19]

    for (int idx = t; idx < 4096; idx += 512) {
        int kc = idx >> 10, rem = idx & 1023, rr = rem >> 4, c = rem & 15;
        WoS[(kc * 64 + rr) * 19 + c] =
            ((const ulonglong2*)Wout)[(size_t)rr * 64 + kc * 16 + c];
    }
    const int tx  = t & 15;
    const int tyr = t >> 4;   // 0..31
    float bo4[4];
    #pragma unroll
    for (int j = 0; j < 4; j++) bo4[j] = __ldg(&bout[tx + 16 * j]);
    __syncthreads();

    for (int tile = 0; tile < 32; tile++) {
        size_t m0 = ((size_t)blockIdx.x * 32 + tile) * 64;
        ull ac[2][4];
        #pragma unroll
        for (int i = 0; i < 2; i++)
            #pragma unroll
            for (int j = 0; j < 4; j++) ac[i][j] = 0ull;

        for (int kc = 0; kc < 4; kc++) {
            __syncthreads();
            for (int idx = t; idx < 1024; idx += 512) {
                int rr = idx >> 4, c = idx & 15;
                HsS[rr * 19 + c] =
                    ((const ulonglong2*)g_hs)[(m0 + rr) * 64 + kc * 16 + c];
            }
            __syncthreads();
            #pragma unroll
            for (int k4 = 0; k4 < 16; k4++) {
                ulonglong2 a0 = HsS[tyr * 19 + k4];
                ulonglong2 a1 = HsS[(tyr + 32) * 19 + k4];
                #pragma unroll
                for (int j = 0; j < 4; j++) {
                    ulonglong2 b2 = WoS[(kc * 64 + tx + 16 * j) * 19 + k4];
                    FMA2(ac[0][j], a0.x, b2.x); FMA2(ac[0][j], a0.y, b2.y);
                    FMA2(ac[1][j], a1.x, b2.x); FMA2(ac[1][j], a1.y, b2.y);
                }
            }
        }
        #pragma unroll
        for (int i = 0; i < 2; i++) {
            size_t m = m0 + tyr + 32 * i;
            #pragma unroll
            for (int j = 0; j < 4; j++)
                out[m * OUTD + tx + 16 * j] = hsum2(ac[i][j]) + bo4[j];
        }
    }
}

// =============================================================
extern "C" void kernel_launch(void* const* d_in, const int* in_sizes, int n_in,
                              void* d_out, int out_size)
{
    (void)in_sizes; (void)n_in; (void)out_size;
    const float* x    = (const float*)d_in[0];
    const float* h0   = (const float*)d_in[1];
    const float* c0   = (const float*)d_in[2];
    const float* Wih  = (const float*)d_in[3];
    const float* Whh  = (const float*)d_in[4];
    const float* b    = (const float*)d_in[5];
    const float* Wout = (const float*)d_in[6];
    const float* bout = (const float*)d_in[7];
    float* out = (float*)d_out;

    const int smB = SM_TOT * 4;   // 200704 B

    cudaFuncSetAttribute(k_lstm, cudaFuncAttributeMaxDynamicSharedMemorySize, smB);

    k_lstm<<<NBG * NUG, 512, smB>>>(x, h0, c0, Whh, Wih, b, Wout, bout, out);
}